// round 3
// baseline (speedup 1.0000x reference)
#include <cuda_runtime.h>
#include <cuda_bf16.h>
#include <cstdint>
#include <cstddef>

// ---------------- problem dims ----------------
#define BATCH 512
#define NIN   2048
#define UNITS 4096
#define KTOT  6144            // NIN + UNITS
#define OFS   (BATCH*UNITS)   // elements per output tensor

// ---------------- GEMM tiling ----------------
#define BM 128
#define BN 128
#define BK 64                 // bf16 K elements per stage (128 B rows)
#define STAGES 4
#define NKS (KTOT/BK)         // 96
#define TILE_BYTES 16384u     // 128 rows x 128 B
#define STAGE_BYTES 32768u
#define GEMM_SMEM (STAGES*STAGE_BYTES + 1024u)

// byte-offset swizzle (SW128-style, conflict-free ldmatrix)
#define SWZ(x) ((x) ^ (((x) >> 3) & 0x70u))

// ---------------- neuron constants ----------------
#define C_EL      (-70.6f)
#define C_THR     (-50.4f)
#define C_DTGLC   ((float)(30.0/281.0))
#define C_INVCAP  ((float)(1.0/281.0))
#define C_DTTAUW  ((float)(1.0/144.0))
#define C_DTATAUW ((float)(4.0/144.0))
#define C_BW      (0.0805f)
#define C_VRST    (-70.6f)
#define C_CLIP    (281.0f)

// ---------------- scratch ----------------
__device__ __nv_bfloat16 g_Apack[(size_t)BATCH * KTOT];
__device__ __nv_bfloat16 g_WT[(size_t)UNITS * KTOT];

// ---------------- helpers ----------------
__device__ __forceinline__ uint32_t smem_u32(const void* p) {
    uint32_t a;
    asm("{ .reg .u64 t; cvta.to.shared.u64 t, %1; cvt.u32.u64 %0, t; }"
        : "=r"(a) : "l"(p));
    return a;
}
__device__ __forceinline__ void cp16(uint32_t saddr, const void* g) {
    asm volatile("cp.async.cg.shared.global [%0], [%1], 16;"
                 :: "r"(saddr), "l"(g));
}
__device__ __forceinline__ void ldmx4(uint32_t& r0, uint32_t& r1,
                                      uint32_t& r2, uint32_t& r3, uint32_t a) {
    asm volatile("ldmatrix.sync.aligned.m8n8.x4.shared.b16 {%0,%1,%2,%3}, [%4];"
                 : "=r"(r0), "=r"(r1), "=r"(r2), "=r"(r3) : "r"(a));
}
__device__ __forceinline__ void mma16816(float& d0, float& d1, float& d2, float& d3,
                                         uint32_t a0, uint32_t a1, uint32_t a2, uint32_t a3,
                                         uint32_t b0, uint32_t b1) {
    asm volatile(
        "mma.sync.aligned.m16n8k16.row.col.f32.bf16.bf16.f32 "
        "{%0,%1,%2,%3}, {%4,%5,%6,%7}, {%8,%9}, {%0,%1,%2,%3};"
        : "+f"(d0), "+f"(d1), "+f"(d2), "+f"(d3)
        : "r"(a0), "r"(a1), "r"(a2), "r"(a3), "r"(b0), "r"(b1));
}

// ---------------- kernel 1: pack [inputs | z] -> bf16 ----------------
__global__ void pack_kernel(const float* __restrict__ inp,
                            const float* __restrict__ z) {
    int idx = blockIdx.x * blockDim.x + threadIdx.x;   // BATCH*KTOT/2
    int b = idx / (KTOT / 2);
    int c = idx - b * (KTOT / 2);
    int k = 2 * c;
    float x0, x1;
    if (k < NIN) {
        const float* p = inp + (size_t)b * NIN + k;
        x0 = p[0]; x1 = p[1];
    } else {
        const float* p = z + (size_t)b * UNITS + (k - NIN);
        x0 = p[0]; x1 = p[1];
    }
    reinterpret_cast<__nv_bfloat162*>(g_Apack)[idx] = __floats2bfloat162_rn(x0, x1);
}

// ---------------- kernel 2: transpose+convert -> WT[n][k] bf16 ----------
__global__ void transpose_kernel(const float* __restrict__ Win,
                                 const float* __restrict__ Wrec) {
    __shared__ float s[32][65];
    int k0 = blockIdx.x * 64;
    int n0 = blockIdx.y * 32;
    int tx = threadIdx.x;   // n-local
    int ty = threadIdx.y;   // 0..7

    #pragma unroll
    for (int i = 0; i < 8; i++) {
        int k = k0 + ty + i * 8;
        int n = n0 + tx;
        float v;
        if (k < NIN) {
            v = Win[(size_t)k * UNITS + n];
        } else {
            int kr = k - NIN;
            v = (kr == n) ? 0.0f : Wrec[(size_t)kr * UNITS + n];
        }
        s[tx][ty + i * 8] = v;
    }
    __syncthreads();

    int t = ty * 32 + tx;
    #pragma unroll
    for (int i = 0; i < 4; i++) {
        int r = i * 8 + (t >> 5);
        int c = t & 31;
        __nv_bfloat162 pk = __floats2bfloat162_rn(s[r][2 * c], s[r][2 * c + 1]);
        reinterpret_cast<__nv_bfloat162*>(g_WT + (size_t)(n0 + r) * KTOT + k0)[c] = pk;
    }
}

// ---------------- stage loader ----------------
__device__ __forceinline__ void load_stage(uint32_t tiles, int tid,
                                           const __nv_bfloat16* Ag,
                                           const __nv_bfloat16* Bg,
                                           int ks, int s) {
    uint32_t abase = tiles + (uint32_t)s * STAGE_BYTES;
    uint32_t bbase = abase + TILE_BYTES;
    const __nv_bfloat16* ag = Ag + ks * BK;
    const __nv_bfloat16* bg = Bg + ks * BK;
    #pragma unroll
    for (int i = 0; i < 4; i++) {
        int id = tid + i * 256;
        int row = id >> 3, cg = id & 7;
        uint32_t off = SWZ((uint32_t)(row * 128 + cg * 16));
        cp16(abase + off, ag + (size_t)row * KTOT + cg * 8);
    }
    #pragma unroll
    for (int i = 0; i < 4; i++) {
        int id = tid + i * 256;
        int row = id >> 3, cg = id & 7;
        uint32_t off = SWZ((uint32_t)(row * 128 + cg * 16));
        cp16(bbase + off, bg + (size_t)row * KTOT + cg * 8);
    }
}

// ---------------- AdEx elementwise ----------------
__device__ __forceinline__ void adex_one(float it, float vo, float wo, float zo,
                                         int ro, float& nv, float& nz,
                                         float& nw, float& nr) {
    float ex = expf((vo - C_THR) * 0.5f);
    ex = fminf(ex, C_CLIP);
    float nv0 = vo - C_DTGLC * (vo - C_EL) + (2.0f * C_DTGLC) * ex
              + (it - wo) * C_INVCAP;
    nv = (zo > 0.5f) ? C_VRST : nv0;
    nw = wo - wo * C_DTTAUW + C_DTATAUW * (vo - C_EL) + C_BW * zo;
    bool sp = (nv > C_THR) && (ro <= 0);
    nz = sp ? 1.0f : 0.0f;
    int nri = ro - 1 + (sp ? 2 : 0);
    nri = nri < 0 ? 0 : (nri > 2 ? 2 : nri);
    nr = (float)nri;
}

// ---------------- kernel 3: HMMA GEMM + AdEx epilogue ----------------
__global__ void __launch_bounds__(256, 1)
adex_gemm_kernel(const float* __restrict__ v_in, const int* __restrict__ r_in,
                 const float* __restrict__ w_in, const float* __restrict__ z_in,
                 float* __restrict__ out) {
    extern __shared__ char smem[];
    uint32_t tiles = (smem_u32(smem) + 1023u) & ~1023u;
    int tid = threadIdx.x;
    int wid = tid >> 5;
    int lane = tid & 31;

    int m0 = (blockIdx.x & 3) * BM;
    int n0 = (blockIdx.x >> 2) * BN;
    int wm = (wid & 1) * 64;    // warp M offset (2 warps in M)
    int wn = (wid >> 1) * 32;   // warp N offset (4 warps in N)

    const __nv_bfloat16* Ag = g_Apack + (size_t)m0 * KTOT;
    const __nv_bfloat16* Bg = g_WT + (size_t)n0 * KTOT;

    float acc[4][4][4];   // [mf][nf][4]
    #pragma unroll
    for (int i = 0; i < 4; i++)
        #pragma unroll
        for (int j = 0; j < 4; j++)
            #pragma unroll
            for (int q = 0; q < 4; q++) acc[i][j][q] = 0.0f;

    // prologue
    #pragma unroll
    for (int s = 0; s < STAGES - 1; ++s) {
        load_stage(tiles, tid, Ag, Bg, s, s);
        asm volatile("cp.async.commit_group;");
    }

    // ldmatrix per-lane address components (within a 16x16 bf16 tile)
    int lrow = lane & 15;          // row within 16
    int lcg  = (lane >> 4) * 16;   // 16B column group

    for (int ks = 0; ks < NKS; ++ks) {
        int s = ks & (STAGES - 1);
        asm volatile("cp.async.wait_group %0;" :: "n"(STAGES - 2));
        __syncthreads();

        // issue next stage loads first (overlap with compute)
        int kn = ks + STAGES - 1;
        if (kn < NKS) load_stage(tiles, tid, Ag, Bg, kn, kn & (STAGES - 1));
        asm volatile("cp.async.commit_group;");

        uint32_t abase = tiles + (uint32_t)s * STAGE_BYTES;
        uint32_t bbase = abase + TILE_BYTES;

        #pragma unroll
        for (int kk = 0; kk < BK / 16; ++kk) {     // 4 k16 steps
            uint32_t af[4][4];
            #pragma unroll
            for (int mf = 0; mf < 4; ++mf) {
                int row = wm + mf * 16 + lrow;
                uint32_t addr = abase + SWZ((uint32_t)(row * 128 + kk * 32 + lcg));
                ldmx4(af[mf][0], af[mf][1], af[mf][2], af[mf][3], addr);
            }
            uint32_t bf[4][2];
            #pragma unroll
            for (int p = 0; p < 2; ++p) {
                int row = wn + p * 16 + lrow;
                uint32_t addr = bbase + SWZ((uint32_t)(row * 128 + kk * 32 + lcg));
                uint32_t r0, r1, r2, r3;
                ldmx4(r0, r1, r2, r3, addr);
                bf[p * 2 + 0][0] = r0; bf[p * 2 + 0][1] = r2;
                bf[p * 2 + 1][0] = r1; bf[p * 2 + 1][1] = r3;
            }
            #pragma unroll
            for (int mf = 0; mf < 4; ++mf)
                #pragma unroll
                for (int nf = 0; nf < 4; ++nf)
                    mma16816(acc[mf][nf][0], acc[mf][nf][1],
                             acc[mf][nf][2], acc[mf][nf][3],
                             af[mf][0], af[mf][1], af[mf][2], af[mf][3],
                             bf[nf][0], bf[nf][1]);
        }
    }

    // ------------- epilogue: registers -> AdEx -> d_out -------------
    int gid = lane >> 2;           // 0..7
    int qn  = (lane & 3) * 2;      // col pair within 8

    #pragma unroll
    for (int mf = 0; mf < 4; ++mf) {
        #pragma unroll
        for (int g = 0; g < 2; ++g) {      // row groups (gid, gid+8)
            int b = m0 + wm + mf * 16 + g * 8 + gid;
            size_t rowbase = (size_t)b * UNITS + n0 + wn;
            #pragma unroll
            for (int nf = 0; nf < 4; ++nf) {
                size_t ofs = rowbase + nf * 8 + qn;
                float2 vv = *reinterpret_cast<const float2*>(v_in + ofs);
                float2 ww = *reinterpret_cast<const float2*>(w_in + ofs);
                float2 zz = *reinterpret_cast<const float2*>(z_in + ofs);
                int2   rr = *reinterpret_cast<const int2*>(r_in + ofs);
                float i0 = acc[mf][nf][g * 2 + 0];
                float i1 = acc[mf][nf][g * 2 + 1];
                float2 ov, oz, ow, orr;
                adex_one(i0, vv.x, ww.x, zz.x, rr.x, ov.x, oz.x, ow.x, orr.x);
                adex_one(i1, vv.y, ww.y, zz.y, rr.y, ov.y, oz.y, ow.y, orr.y);
                *reinterpret_cast<float2*>(out + 0 * (size_t)OFS + ofs) = ov;
                *reinterpret_cast<float2*>(out + 1 * (size_t)OFS + ofs) = oz;
                *reinterpret_cast<float2*>(out + 2 * (size_t)OFS + ofs) = ow;
                *reinterpret_cast<float2*>(out + 3 * (size_t)OFS + ofs) = orr;
            }
        }
    }
}

// ---------------- launch ----------------
extern "C" void kernel_launch(void* const* d_in, const int* in_sizes, int n_in,
                              void* d_out, int out_size) {
    const float* inputs = (const float*)d_in[0];
    const float* v      = (const float*)d_in[1];
    const int*   r      = (const int*)d_in[2];
    const float* w      = (const float*)d_in[3];
    const float* z      = (const float*)d_in[4];
    const float* Win    = (const float*)d_in[5];
    const float* Wrec   = (const float*)d_in[6];
    float* out = (float*)d_out;
    (void)in_sizes; (void)n_in; (void)out_size;

    cudaFuncSetAttribute(adex_gemm_kernel,
                         cudaFuncAttributeMaxDynamicSharedMemorySize, GEMM_SMEM);

    pack_kernel<<<(BATCH * KTOT / 2) / 256, 256>>>(inputs, z);
    transpose_kernel<<<dim3(KTOT / 64, UNITS / 32), dim3(32, 8)>>>(Win, Wrec);
    adex_gemm_kernel<<<128, 256, GEMM_SMEM>>>(v, r, w, z, out);
}

// round 4
// speedup vs baseline: 1.0460x; 1.0460x over previous
#include <cuda_runtime.h>
#include <cuda_bf16.h>
#include <cstdint>
#include <cstddef>

// ---------------- problem dims ----------------
#define BATCH 512
#define NIN   2048
#define UNITS 4096
#define KTOT  6144            // NIN + UNITS
#define OFS   (BATCH*UNITS)   // elements per output tensor

// ---------------- GEMM tiling ----------------
#define BM 128
#define BN 128
#define BK 128                // bf16 K elements per stage (256 B rows)
#define STAGES 3
#define NKS (KTOT/BK)         // 48
#define TILE_BYTES 32768u     // 128 rows x 256 B
#define STAGE_BYTES 65536u
#define GEMM_SMEM (STAGES*STAGE_BYTES + 1024u)   // 197632

// swizzle for 256B-pitch rows: XOR bits[8:10] into bits[4:6]
#define SWZB(x) ((x) ^ (((x) >> 4) & 0x70u))

#define TBLK (KTOT/64)        // 96  transpose blocks in k
#define NTRB (TBLK*(UNITS/32))// 12288 transpose blocks
#define NPKB (BATCH*KTOT/512) // 6144 pack blocks

// ---------------- neuron constants ----------------
#define C_EL      (-70.6f)
#define C_THR     (-50.4f)
#define C_DTGLC   ((float)(30.0/281.0))
#define C_INVCAP  ((float)(1.0/281.0))
#define C_DTTAUW  ((float)(1.0/144.0))
#define C_DTATAUW ((float)(4.0/144.0))
#define C_BW      (0.0805f)
#define C_VRST    (-70.6f)
#define C_CLIP    (281.0f)

// ---------------- scratch ----------------
__device__ __nv_bfloat16 g_Apack[(size_t)BATCH * KTOT];
__device__ __nv_bfloat16 g_WT[(size_t)UNITS * KTOT];

// ---------------- helpers ----------------
__device__ __forceinline__ uint32_t smem_u32(const void* p) {
    uint32_t a;
    asm("{ .reg .u64 t; cvta.to.shared.u64 t, %1; cvt.u32.u64 %0, t; }"
        : "=r"(a) : "l"(p));
    return a;
}
__device__ __forceinline__ void cp16(uint32_t saddr, const void* g) {
    asm volatile("cp.async.cg.shared.global [%0], [%1], 16;"
                 :: "r"(saddr), "l"(g));
}
__device__ __forceinline__ void ldmx4(uint32_t& r0, uint32_t& r1,
                                      uint32_t& r2, uint32_t& r3, uint32_t a) {
    asm volatile("ldmatrix.sync.aligned.m8n8.x4.shared.b16 {%0,%1,%2,%3}, [%4];"
                 : "=r"(r0), "=r"(r1), "=r"(r2), "=r"(r3) : "r"(a));
}
__device__ __forceinline__ void mma16816(float& d0, float& d1, float& d2, float& d3,
                                         uint32_t a0, uint32_t a1, uint32_t a2, uint32_t a3,
                                         uint32_t b0, uint32_t b1) {
    asm volatile(
        "mma.sync.aligned.m16n8k16.row.col.f32.bf16.bf16.f32 "
        "{%0,%1,%2,%3}, {%4,%5,%6,%7}, {%8,%9}, {%0,%1,%2,%3};"
        : "+f"(d0), "+f"(d1), "+f"(d2), "+f"(d3)
        : "r"(a0), "r"(a1), "r"(a2), "r"(a3), "r"(b0), "r"(b1));
}

// ---------------- kernel 1: fused prep (transpose + pack) ----------------
// blocks [0, NTRB): transpose+convert weights -> g_WT[n][k] bf16 (diag=0)
// blocks [NTRB, NTRB+NPKB): pack [inputs|z] -> g_Apack bf16
__global__ void __launch_bounds__(256)
prep_kernel(const float* __restrict__ inp, const float* __restrict__ z,
            const float* __restrict__ Win, const float* __restrict__ Wrec) {
    __shared__ float s[32][65];
    int blk = blockIdx.x;
    int tid = threadIdx.x;

    if (blk < NTRB) {
        int k0 = (blk % TBLK) * 64;
        int n0 = (blk / TBLK) * 32;
        int tx = tid & 31;    // n-local
        int ty = tid >> 5;    // 0..7

        #pragma unroll
        for (int i = 0; i < 8; i++) {
            int k = k0 + ty + i * 8;
            int n = n0 + tx;
            float v;
            if (k < NIN) {
                v = Win[(size_t)k * UNITS + n];
            } else {
                int kr = k - NIN;
                v = (kr == n) ? 0.0f : Wrec[(size_t)kr * UNITS + n];
            }
            s[tx][ty + i * 8] = v;
        }
        __syncthreads();

        #pragma unroll
        for (int i = 0; i < 4; i++) {
            int r = i * 8 + (tid >> 5);
            int c = tid & 31;
            __nv_bfloat162 pk = __floats2bfloat162_rn(s[r][2 * c], s[r][2 * c + 1]);
            reinterpret_cast<__nv_bfloat162*>(g_WT + (size_t)(n0 + r) * KTOT + k0)[c] = pk;
        }
    } else {
        int idx = (blk - NTRB) * 256 + tid;   // over BATCH*KTOT/2
        int b = idx / (KTOT / 2);
        int c = idx - b * (KTOT / 2);
        int k = 2 * c;
        float x0, x1;
        if (k < NIN) {
            const float* p = inp + (size_t)b * NIN + k;
            x0 = p[0]; x1 = p[1];
        } else {
            const float* p = z + (size_t)b * UNITS + (k - NIN);
            x0 = p[0]; x1 = p[1];
        }
        reinterpret_cast<__nv_bfloat162*>(g_Apack)[idx] = __floats2bfloat162_rn(x0, x1);
    }
}

// ---------------- stage loader (256 threads, 128x128 A + 128x128 B) -------
__device__ __forceinline__ void load_stage(uint32_t tiles, int tid,
                                           const __nv_bfloat16* Ag,
                                           const __nv_bfloat16* Bg,
                                           int ks, int s) {
    uint32_t abase = tiles + (uint32_t)s * STAGE_BYTES;
    uint32_t bbase = abase + TILE_BYTES;
    const __nv_bfloat16* ag = Ag + ks * BK;
    const __nv_bfloat16* bg = Bg + ks * BK;
    #pragma unroll
    for (int i = 0; i < 8; i++) {
        int id = tid + i * 256;            // 0..2047
        int row = id >> 4, cg = id & 15;   // 128 rows x 16 chunks(16B)
        uint32_t off = SWZB((uint32_t)(row * 256 + cg * 16));
        cp16(abase + off, ag + (size_t)row * KTOT + cg * 8);
    }
    #pragma unroll
    for (int i = 0; i < 8; i++) {
        int id = tid + i * 256;
        int row = id >> 4, cg = id & 15;
        uint32_t off = SWZB((uint32_t)(row * 256 + cg * 16));
        cp16(bbase + off, bg + (size_t)row * KTOT + cg * 8);
    }
}

// ---------------- AdEx elementwise ----------------
__device__ __forceinline__ void adex_one(float it, float vo, float wo, float zo,
                                         int ro, float& nv, float& nz,
                                         float& nw, float& nr) {
    float ex = expf((vo - C_THR) * 0.5f);
    ex = fminf(ex, C_CLIP);
    float nv0 = vo - C_DTGLC * (vo - C_EL) + (2.0f * C_DTGLC) * ex
              + (it - wo) * C_INVCAP;
    nv = (zo > 0.5f) ? C_VRST : nv0;
    nw = wo - wo * C_DTTAUW + C_DTATAUW * (vo - C_EL) + C_BW * zo;
    bool sp = (nv > C_THR) && (ro <= 0);
    nz = sp ? 1.0f : 0.0f;
    int nri = ro - 1 + (sp ? 2 : 0);
    nri = nri < 0 ? 0 : (nri > 2 ? 2 : nri);
    nr = (float)nri;
}

// ---------------- kernel 2: HMMA GEMM + AdEx epilogue ----------------
__global__ void __launch_bounds__(256, 1)
adex_gemm_kernel(const float* __restrict__ v_in, const int* __restrict__ r_in,
                 const float* __restrict__ w_in, const float* __restrict__ z_in,
                 float* __restrict__ out) {
    extern __shared__ char smem[];
    uint32_t tiles = (smem_u32(smem) + 1023u) & ~1023u;
    int tid = threadIdx.x;
    int wid = tid >> 5;
    int lane = tid & 31;

    int m0 = (blockIdx.x & 3) * BM;
    int n0 = (blockIdx.x >> 2) * BN;
    int wm = (wid & 1) * 64;    // 2 warps in M
    int wn = (wid >> 1) * 32;   // 4 warps in N

    const __nv_bfloat16* Ag = g_Apack + (size_t)m0 * KTOT;
    const __nv_bfloat16* Bg = g_WT + (size_t)n0 * KTOT;

    float acc[4][4][4];
    #pragma unroll
    for (int i = 0; i < 4; i++)
        #pragma unroll
        for (int j = 0; j < 4; j++)
            #pragma unroll
            for (int q = 0; q < 4; q++) acc[i][j][q] = 0.0f;

    // prologue: fill stages 0..STAGES-2
    #pragma unroll
    for (int s = 0; s < STAGES - 1; ++s) {
        load_stage(tiles, tid, Ag, Bg, s, s);
        asm volatile("cp.async.commit_group;");
    }

    // per-lane ldmatrix row/col components
    int lrow = lane & 15;
    int lcg  = (lane >> 4) * 16;

    // per-lane byte offsets within a tile (before swizzle, before kk shift)
    uint32_t aoff[4], boff[2];
    #pragma unroll
    for (int mf = 0; mf < 4; ++mf)
        aoff[mf] = (uint32_t)((wm + mf * 16 + lrow) * 256 + lcg);
    #pragma unroll
    for (int p = 0; p < 2; ++p)
        boff[p] = (uint32_t)((wn + p * 16 + lrow) * 256 + lcg);

    int s = 0, sn = STAGES - 1;
    for (int ks = 0; ks < NKS; ++ks) {
        asm volatile("cp.async.wait_group %0;" :: "n"(STAGES - 2));
        __syncthreads();

        // issue next stage (into the stage consumed last iteration)
        int kn = ks + STAGES - 1;
        if (kn < NKS) load_stage(tiles, tid, Ag, Bg, kn, sn);
        asm volatile("cp.async.commit_group;");

        uint32_t abase = tiles + (uint32_t)s * STAGE_BYTES;
        uint32_t bbase = abase + TILE_BYTES;

        uint32_t af[2][4][4], bfr[2][4][2];

        // load fragments for kk=0 into buffer 0
        #pragma unroll
        for (int mf = 0; mf < 4; ++mf)
            ldmx4(af[0][mf][0], af[0][mf][1], af[0][mf][2], af[0][mf][3],
                  abase + SWZB(aoff[mf]));
        #pragma unroll
        for (int p = 0; p < 2; ++p) {
            uint32_t r0, r1, r2, r3;
            ldmx4(r0, r1, r2, r3, bbase + SWZB(boff[p]));
            bfr[0][p * 2 + 0][0] = r0; bfr[0][p * 2 + 0][1] = r2;
            bfr[0][p * 2 + 1][0] = r1; bfr[0][p * 2 + 1][1] = r3;
        }

        #pragma unroll
        for (int kk = 0; kk < BK / 16; ++kk) {   // 8 k-steps
            int cur = kk & 1, nxt = cur ^ 1;
            if (kk < BK / 16 - 1) {
                uint32_t kb = (uint32_t)((kk + 1) * 32);
                #pragma unroll
                for (int mf = 0; mf < 4; ++mf)
                    ldmx4(af[nxt][mf][0], af[nxt][mf][1],
                          af[nxt][mf][2], af[nxt][mf][3],
                          abase + SWZB(aoff[mf] + kb));
                #pragma unroll
                for (int p = 0; p < 2; ++p) {
                    uint32_t r0, r1, r2, r3;
                    ldmx4(r0, r1, r2, r3, bbase + SWZB(boff[p] + kb));
                    bfr[nxt][p * 2 + 0][0] = r0; bfr[nxt][p * 2 + 0][1] = r2;
                    bfr[nxt][p * 2 + 1][0] = r1; bfr[nxt][p * 2 + 1][1] = r3;
                }
            }
            #pragma unroll
            for (int mf = 0; mf < 4; ++mf)
                #pragma unroll
                for (int nf = 0; nf < 4; ++nf)
                    mma16816(acc[mf][nf][0], acc[mf][nf][1],
                             acc[mf][nf][2], acc[mf][nf][3],
                             af[cur][mf][0], af[cur][mf][1],
                             af[cur][mf][2], af[cur][mf][3],
                             bfr[cur][nf][0], bfr[cur][nf][1]);
        }

        s = (s + 1 == STAGES) ? 0 : s + 1;
        sn = (sn + 1 == STAGES) ? 0 : sn + 1;
    }

    // ------------- epilogue: registers -> AdEx -> d_out -------------
    int gid = lane >> 2;
    int qn  = (lane & 3) * 2;

    #pragma unroll
    for (int mf = 0; mf < 4; ++mf) {
        #pragma unroll
        for (int g = 0; g < 2; ++g) {
            int b = m0 + wm + mf * 16 + g * 8 + gid;
            size_t rowbase = (size_t)b * UNITS + n0 + wn;
            #pragma unroll
            for (int nf = 0; nf < 4; ++nf) {
                size_t ofs = rowbase + nf * 8 + qn;
                float2 vv = *reinterpret_cast<const float2*>(v_in + ofs);
                float2 ww = *reinterpret_cast<const float2*>(w_in + ofs);
                float2 zz = *reinterpret_cast<const float2*>(z_in + ofs);
                int2   rr = *reinterpret_cast<const int2*>(r_in + ofs);
                float i0 = acc[mf][nf][g * 2 + 0];
                float i1 = acc[mf][nf][g * 2 + 1];
                float2 ov, oz, ow, orr;
                adex_one(i0, vv.x, ww.x, zz.x, rr.x, ov.x, oz.x, ow.x, orr.x);
                adex_one(i1, vv.y, ww.y, zz.y, rr.y, ov.y, oz.y, ow.y, orr.y);
                *reinterpret_cast<float2*>(out + 0 * (size_t)OFS + ofs) = ov;
                *reinterpret_cast<float2*>(out + 1 * (size_t)OFS + ofs) = oz;
                *reinterpret_cast<float2*>(out + 2 * (size_t)OFS + ofs) = ow;
                *reinterpret_cast<float2*>(out + 3 * (size_t)OFS + ofs) = orr;
            }
        }
    }
}

// ---------------- launch ----------------
extern "C" void kernel_launch(void* const* d_in, const int* in_sizes, int n_in,
                              void* d_out, int out_size) {
    const float* inputs = (const float*)d_in[0];
    const float* v      = (const float*)d_in[1];
    const int*   r      = (const int*)d_in[2];
    const float* w      = (const float*)d_in[3];
    const float* z      = (const float*)d_in[4];
    const float* Win    = (const float*)d_in[5];
    const float* Wrec   = (const float*)d_in[6];
    float* out = (float*)d_out;
    (void)in_sizes; (void)n_in; (void)out_size;

    cudaFuncSetAttribute(adex_gemm_kernel,
                         cudaFuncAttributeMaxDynamicSharedMemorySize, GEMM_SMEM);

    prep_kernel<<<NTRB + NPKB, 256>>>(inputs, z, Win, Wrec);
    adex_gemm_kernel<<<128, 256, GEMM_SMEM>>>(v, r, w, z, out);
}

// round 5
// speedup vs baseline: 1.3829x; 1.3221x over previous
#include <cuda_runtime.h>
#include <cuda_bf16.h>
#include <cstdint>
#include <cstddef>

#define BATCH 512
#define NIN   2048
#define UNITS 4096
#define KTOT  6144
#define OFS   (BATCH*UNITS)

#define BM 128
#define BN 128
#define BK 128
#define STAGES 3
#define NKS (KTOT/BK)
#define TILE_BYTES 32768u
#define STAGE_BYTES 65536u
#define GEMM_SMEM (STAGES*STAGE_BYTES + 1024u)

#define SWZB(x) ((x) ^ (((x) >> 4) & 0x70u))

#define NWCB ((KTOT*UNITS/4)/256)
#define NPKB (BATCH*KTOT/512)
#define NDGB (UNITS/256)

#define C_EL      (-70.6f)
#define C_THR     (-50.4f)
#define C_DTGLC   ((float)(30.0/281.0))
#define C_INVCAP  ((float)(1.0/281.0))
#define C_DTTAUW  ((float)(1.0/144.0))
#define C_DTATAUW ((float)(4.0/144.0))
#define C_BW      (0.0805f)
#define C_VRST    (-70.6f)
#define C_CLIP    (281.0f)

__device__ __nv_bfloat16 g_Apack[(size_t)BATCH * KTOT];
__device__ __nv_bfloat16 g_Wbf[(size_t)KTOT * UNITS];
__device__ float g_diag[UNITS];

__device__ __forceinline__ uint32_t smem_u32(const void* p) {
    uint32_t a;
    asm("{ .reg .u64 t; cvta.to.shared.u64 t, %1; cvt.u32.u64 %0, t; }"
        : "=r"(a) : "l"(p));
    return a;
}
__device__ __forceinline__ void cp16(uint32_t saddr, const void* g) {
    asm volatile("cp.async.cg.shared.global [%0], [%1], 16;"
                 :: "r"(saddr), "l"(g));
}
__device__ __forceinline__ void ldmx4(uint32_t& r0, uint32_t& r1,
                                      uint32_t& r2, uint32_t& r3, uint32_t a) {
    asm volatile("ldmatrix.sync.aligned.m8n8.x4.shared.b16 {%0,%1,%2,%3}, [%4];"
                 : "=r"(r0), "=r"(r1), "=r"(r2), "=r"(r3) : "r"(a));
}
__device__ __forceinline__ void ldmx4t(uint32_t& r0, uint32_t& r1,
                                       uint32_t& r2, uint32_t& r3, uint32_t a) {
    asm volatile("ldmatrix.sync.aligned.m8n8.x4.trans.shared.b16 {%0,%1,%2,%3}, [%4];"
                 : "=r"(r0), "=r"(r1), "=r"(r2), "=r"(r3) : "r"(a));
}
__device__ __forceinline__ void mma16816(float& d0, float& d1, float& d2, float& d3,
                                         uint32_t a0, uint32_t a1, uint32_t a2, uint32_t a3,
                                         uint32_t b0, uint32_t b1) {
    asm volatile(
        "mma.sync.aligned.m16n8k16.row.col.f32.bf16.bf16.f32 "
        "{%0,%1,%2,%3}, {%4,%5,%6,%7}, {%8,%9}, {%0,%1,%2,%3};"
        : "+f"(d0), "+f"(d1), "+f"(d2), "+f"(d3)
        : "r"(a0), "r"(a1), "r"(a2), "r"(a3), "r"(b0), "r"(b1));
}

__global__ void __launch_bounds__(256)
prep_kernel(const float* __restrict__ inp, const float* __restrict__ z,
            const float* __restrict__ Win, const float* __restrict__ Wrec) {
    int blk = blockIdx.x;
    int tid = threadIdx.x;

    if (blk < NWCB) {
        size_t e = ((size_t)blk * 256 + tid) * 4;
        const float* src = (e < (size_t)NIN * UNITS)
                         ? (Win + e) : (Wrec + (e - (size_t)NIN * UNITS));
        float4 f = *reinterpret_cast<const float4*>(src);
        __nv_bfloat162 p0 = __floats2bfloat162_rn(f.x, f.y);
        __nv_bfloat162 p1 = __floats2bfloat162_rn(f.z, f.w);
        uint2 pk;
        pk.x = *reinterpret_cast<uint32_t*>(&p0);
        pk.y = *reinterpret_cast<uint32_t*>(&p1);
        reinterpret_cast<uint2*>(g_Wbf)[e / 4] = pk;
    } else if (blk < NWCB + NPKB) {
        int idx = (blk - NWCB) * 256 + tid;
        int b = idx / (KTOT / 2);
        int c = idx - b * (KTOT / 2);
        int k = 2 * c;
        float x0, x1;
        if (k < NIN) {
            const float* p = inp + (size_t)b * NIN + k;
            x0 = p[0]; x1 = p[1];
        } else {
            const float* p = z + (size_t)b * UNITS + (k - NIN);
            x0 = p[0]; x1 = p[1];
        }
        reinterpret_cast<__nv_bfloat162*>(g_Apack)[idx] = __floats2bfloat162_rn(x0, x1);
    } else {
        int n = (blk - NWCB - NPKB) * 256 + tid;
        g_diag[n] = __bfloat162float(__float2bfloat16(Wrec[(size_t)n * UNITS + n]));
    }
}

__device__ __forceinline__ void load_stage(uint32_t tiles, int tid,
                                           const __nv_bfloat16* Ag,
                                           const __nv_bfloat16* Bg,
                                           int ks, int s) {
    uint32_t abase = tiles + (uint32_t)s * STAGE_BYTES;
    uint32_t bbase = abase + TILE_BYTES;
    const __nv_bfloat16* ag = Ag + ks * BK;
    const __nv_bfloat16* bg = Bg + (size_t)(ks * BK) * UNITS;
    #pragma unroll
    for (int i = 0; i < 8; i++) {
        int id = tid + i * 256;
        int row = id >> 4, cg = id & 15;
        uint32_t off = SWZB((uint32_t)(row * 256 + cg * 16));
        cp16(abase + off, ag + (size_t)row * KTOT + cg * 8);
    }
    #pragma unroll
    for (int i = 0; i < 8; i++) {
        int id = tid + i * 256;
        int row = id >> 4, cg = id & 15;
        uint32_t off = SWZB((uint32_t)(row * 256 + cg * 16));
        cp16(bbase + off, bg + (size_t)row * UNITS + cg * 8);
    }
}

__device__ __forceinline__ void adex_one(float it, float vo, float wo, float zo,
                                         int ro, float& nv, float& nz,
                                         float& nw, float& nr) {
    float ex = expf((vo - C_THR) * 0.5f);
    ex = fminf(ex, C_CLIP);
    float nv0 = vo - C_DTGLC * (vo - C_EL) + (2.0f * C_DTGLC) * ex
              + (it - wo) * C_INVCAP;
    nv = (zo > 0.5f) ? C_VRST : nv0;
    nw = wo - wo * C_DTTAUW + C_DTATAUW * (vo - C_EL) + C_BW * zo;
    bool sp = (nv > C_THR) && (ro <= 0);
    nz = sp ? 1.0f : 0.0f;
    int nri = ro - 1 + (sp ? 2 : 0);
    nri = nri < 0 ? 0 : (nri > 2 ? 2 : nri);
    nr = (float)nri;
}

__global__ void __launch_bounds__(256, 1)
adex_gemm_kernel(const float* __restrict__ v_in, const int* __restrict__ r_in,
                 const float* __restrict__ w_in, const float* __restrict__ z_in,
                 float* __restrict__ out) {
    extern __shared__ char smem[];
    uint32_t tiles = (smem_u32(smem) + 1023u) & ~1023u;
    int tid = threadIdx.x;
    int wid = tid >> 5;
    int lane = tid & 31;

    int m0 = (blockIdx.x & 3) * BM;
    int n0 = (blockIdx.x >> 2) * BN;
    int wm = (wid & 1) * 64;
    int wn = (wid >> 1) * 32;

    const __nv_bfloat16* Ag = g_Apack + (size_t)m0 * KTOT;
    const __nv_bfloat16* Bg = g_Wbf + n0;

    float acc[4][4][4];
    #pragma unroll
    for (int i = 0; i < 4; i++)
        #pragma unroll
        for (int j = 0; j < 4; j++)
            #pragma unroll
            for (int q = 0; q < 4; q++) acc[i][j][q] = 0.0f;

    #pragma unroll
    for (int s = 0; s < STAGES - 1; ++s) {
        load_stage(tiles, tid, Ag, Bg, s, s);
        asm volatile("cp.async.commit_group;");
    }

    int lrow = lane & 15;
    int lcg  = (lane >> 4) * 16;

    uint32_t aoff[4];
    #pragma unroll
    for (int mf = 0; mf < 4; ++mf)
        aoff[mf] = (uint32_t)((wm + mf * 16 + lrow) * 256 + lcg);
    uint32_t boff[2];
    #pragma unroll
    for (int p = 0; p < 2; ++p)
        boff[p] = (uint32_t)(lrow * 256 + wn * 2 + p * 32 + lcg);

    int s = 0, sn = STAGES - 1;
    for (int ks = 0; ks < NKS; ++ks) {
        asm volatile("cp.async.wait_group %0;" :: "n"(STAGES - 2));
        __syncthreads();

        int kn = ks + STAGES - 1;
        if (kn < NKS) load_stage(tiles, tid, Ag, Bg, kn, sn);
        asm volatile("cp.async.commit_group;");

        uint32_t abase = tiles + (uint32_t)s * STAGE_BYTES;
        uint32_t bbase = abase + TILE_BYTES;

        uint32_t af[2][4][4], bfr[2][4][2];

        #pragma unroll
        for (int mf = 0; mf < 4; ++mf)
            ldmx4(af[0][mf][0], af[0][mf][1], af[0][mf][2], af[0][mf][3],
                  abase + SWZB(aoff[mf]));
        #pragma unroll
        for (int p = 0; p < 2; ++p) {
            uint32_t r0, r1, r2, r3;
            ldmx4t(r0, r1, r2, r3, bbase + SWZB(boff[p]));
            bfr[0][p * 2 + 0][0] = r0; bfr[0][p * 2 + 0][1] = r1;
            bfr[0][p * 2 + 1][0] = r2; bfr[0][p * 2 + 1][1] = r3;
        }

        #pragma unroll
        for (int kk = 0; kk < BK / 16; ++kk) {
            int cur = kk & 1, nxt = cur ^ 1;
            if (kk < BK / 16 - 1) {
                uint32_t kba = (uint32_t)((kk + 1) * 32);
                uint32_t kbb = (uint32_t)((kk + 1) * 4096);
                #pragma unroll
                for (int mf = 0; mf < 4; ++mf)
                    ldmx4(af[nxt][mf][0], af[nxt][mf][1],
                          af[nxt][mf][2], af[nxt][mf][3],
                          abase + SWZB(aoff[mf] + kba));
                #pragma unroll
                for (int p = 0; p < 2; ++p) {
                    uint32_t r0, r1, r2, r3;
                    ldmx4t(r0, r1, r2, r3, bbase + SWZB(boff[p] + kbb));
                    bfr[nxt][p * 2 + 0][0] = r0; bfr[nxt][p * 2 + 0][1] = r1;
                    bfr[nxt][p * 2 + 1][0] = r2; bfr[nxt][p * 2 + 1][1] = r3;
                }
            }
            #pragma unroll
            for (int mf = 0; mf < 4; ++mf)
                #pragma unroll
                for (int nf = 0; nf < 4; ++nf)
                    mma16816(acc[mf][nf][0], acc[mf][nf][1],
                             acc[mf][nf][2], acc[mf][nf][3],
                             af[cur][mf][0], af[cur][mf][1],
                             af[cur][mf][2], af[cur][mf][3],
                             bfr[cur][nf][0], bfr[cur][nf][1]);
        }

        s = (s + 1 == STAGES) ? 0 : s + 1;
        sn = (sn + 1 == STAGES) ? 0 : sn + 1;
    }

    int gid = lane >> 2;
    int qn  = (lane & 3) * 2;

    #pragma unroll
    for (int mf = 0; mf < 4; ++mf) {
        #pragma unroll
        for (int g = 0; g < 2; ++g) {
            int b = m0 + wm + mf * 16 + g * 8 + gid;
            size_t rowbase = (size_t)b * UNITS + n0 + wn;
            #pragma unroll
            for (int nf = 0; nf < 4; ++nf) {
                size_t ofs = rowbase + nf * 8 + qn;
                int ncol = n0 + wn + nf * 8 + qn;
                float2 vv = *reinterpret_cast<const float2*>(v_in + ofs);
                float2 ww = *reinterpret_cast<const float2*>(w_in + ofs);
                float2 zz = *reinterpret_cast<const float2*>(z_in + ofs);
                int2   rr = *reinterpret_cast<const int2*>(r_in + ofs);
                float2 dg = *reinterpret_cast<const float2*>(g_diag + ncol);
                float i0 = acc[mf][nf][g * 2 + 0] - zz.x * dg.x;
                float i1 = acc[mf][nf][g * 2 + 1] - zz.y * dg.y;
                float2 ov, oz, ow, orr;
                adex_one(i0, vv.x, ww.x, zz.x, rr.x, ov.x, oz.x, ow.x, orr.x);
                adex_one(i1, vv.y, ww.y, zz.y, rr.y, ov.y, oz.y, ow.y, orr.y);
                *reinterpret_cast<float2*>(out + 0 * (size_t)OFS + ofs) = ov;
                *reinterpret_cast<float2*>(out + 1 * (size_t)OFS + ofs) = oz;
                *reinterpret_cast<float2*>(out + 2 * (size_t)OFS + ofs) = ow;
                *reinterpret_cast<float2*>(out + 3 * (size_t)OFS + ofs) = orr;
            }
        }
    }
}

extern "C" void kernel_launch(void* const* d_in, const int* in_sizes, int n_in,
                              void* d_out, int out_size) {
    const float* inputs = (const float*)d_in[0];
    const float* v      = (const float*)d_in[1];
    const int*   r      = (const int*)d_in[2];
    const float* w      = (const float*)d_in[3];
    const float* z      = (const float*)d_in[4];
    const float* Win    = (const float*)d_in[5];
    const float* Wrec   = (const float*)d_in[6];
    float* out = (float*)d_out;
    (void)in_sizes; (void)n_in; (void)out_size;

    cudaFuncSetAttribute(adex_gemm_kernel,
                         cudaFuncAttributeMaxDynamicSharedMemorySize, GEMM_SMEM);

    prep_kernel<<<NWCB + NPKB + NDGB, 256>>>(inputs, z, Win, Wrec);
    adex_gemm_kernel<<<128, 256, GEMM_SMEM>>>(v, r, w, z, out);
}